// round 1
// baseline (speedup 1.0000x reference)
#include <cuda_runtime.h>

#define BB 4
#define SS 1025
#define SQ 1024
#define EE 1024
#define HH 16
#define DH 64
#define BH (BB*HH)
#define EPSF 1e-5f

// ---- scratch (allocation-free: device globals) ----
__device__ float QS[BH*SQ*DH];     // 16 MB
__device__ float KS[BH*SQ*DH];
__device__ float VS[BH*SQ*DH];
__device__ float CPS[BH*SQ*DH];    // cls_proj heads
__device__ float AC2O[(size_t)BH*SQ*SQ];  // 256 MB attn_c2o
__device__ float VALS[BB*SS*EE];   // pre-output values (cls row 0 + tokens)
__device__ float CVEC[BH*DH];      // c vector per (b,h)
__device__ float CN2[BH];          // clipped |c|^2
__device__ float QN2[BH*SQ];       // clipped |q|^2 per row
__device__ float CQg[BH*SQ];       // c . q_j per key j

// ============================================================
// Projection GEMM: out[token, j] = xt[token,:] . W[j,:] + b[j]
// scattered to head layout [bh][i][d]. grid(16, 64, 4) block 256
// ============================================================
__global__ void proj_kernel(const float* __restrict__ x,
                            const float* __restrict__ W0, const float* __restrict__ b0,
                            const float* __restrict__ W1, const float* __restrict__ b1,
                            const float* __restrict__ W2, const float* __restrict__ b2,
                            const float* __restrict__ W3, const float* __restrict__ b3)
{
    int w = blockIdx.z;
    const float* Wm   = (w==0)?W0:(w==1)?W1:(w==2)?W2:W3;
    const float* bias = (w==0)?b0:(w==1)?b1:(w==2)?b2:b3;
    float* dst        = (w==0)?QS:(w==1)?KS:(w==2)?VS:CPS;

    __shared__ float As[16][65];
    __shared__ float Bs[16][65];
    int tid = threadIdx.x;
    int m0 = blockIdx.y*64, n0 = blockIdx.x*64;
    int tm = (tid>>4)<<2;
    int tn = (tid&15)<<2;
    float acc[4][4] = {};
    int lr = tid>>2;
    int lk = (tid&3)<<2;

    int t  = m0 + lr;
    int b_ = t >> 10, i_ = t & 1023;
    const float* arow = x  + (size_t)(b_*SS + i_ + 1)*EE;   // xt row (skip cls tok)
    const float* brow = Wm + (size_t)(n0 + lr)*EE;

    for (int kt = 0; kt < EE; kt += 16) {
        float4 av = *(const float4*)(arow + kt + lk);
        float4 bv = *(const float4*)(brow + kt + lk);
        As[lk+0][lr]=av.x; As[lk+1][lr]=av.y; As[lk+2][lr]=av.z; As[lk+3][lr]=av.w;
        Bs[lk+0][lr]=bv.x; Bs[lk+1][lr]=bv.y; Bs[lk+2][lr]=bv.z; Bs[lk+3][lr]=bv.w;
        __syncthreads();
        #pragma unroll
        for (int k = 0; k < 16; k++) {
            float a[4], b[4];
            #pragma unroll
            for (int p = 0; p < 4; p++) { a[p] = As[k][tm+p]; b[p] = Bs[k][tn+p]; }
            #pragma unroll
            for (int p = 0; p < 4; p++)
                #pragma unroll
                for (int q = 0; q < 4; q++) acc[p][q] += a[p]*b[q];
        }
        __syncthreads();
    }
    #pragma unroll
    for (int p = 0; p < 4; p++) {
        int tok = m0 + tm + p;
        int bb2 = tok >> 10, ii2 = tok & 1023;
        #pragma unroll
        for (int q = 0; q < 4; q++) {
            int j = n0 + tn + q;
            int h2 = j >> 6, d2 = j & 63;
            dst[(size_t)((bb2*HH + h2)*SQ + ii2)*DH + d2] = acc[p][q] + bias[j];
        }
    }
}

// ============================================================
// cls token projection: c[bh][d] = x[b,0,:] . Wq[h*64+d,:] + bq
// plus CN2. grid BH, block 64
// ============================================================
__global__ void clsproj_kernel(const float* __restrict__ x,
                               const float* __restrict__ Wq,
                               const float* __restrict__ bq)
{
    int bh = blockIdx.x;
    int b_ = bh / HH, h_ = bh % HH;
    int d  = threadIdx.x;
    int j  = h_*DH + d;
    const float* xr = x  + (size_t)(b_*SS)*EE;
    const float* wr = Wq + (size_t)j*EE;
    float s = 0.f;
    for (int e = 0; e < EE; e += 4) {
        float4 xv = *(const float4*)(xr + e);
        float4 wv = *(const float4*)(wr + e);
        s += xv.x*wv.x + xv.y*wv.y + xv.z*wv.z + xv.w*wv.w;
    }
    s += bq[j];
    CVEC[bh*DH + d] = s;
    __shared__ float red[64];
    red[d] = s*s; __syncthreads();
    for (int o = 32; o > 0; o >>= 1) { if (d < o) red[d] += red[d+o]; __syncthreads(); }
    if (d == 0) CN2[bh] = fmaxf(red[0], EPSF);
}

// ============================================================
// per-row q stats: QN2 (clipped) and CQ = c.q . warp per row.
// grid BH*SQ/8, block 256
// ============================================================
__global__ void qstats_kernel()
{
    int row  = blockIdx.x*8 + (threadIdx.x >> 5);
    int lane = threadIdx.x & 31;
    int bh   = row >> 10;
    const float* qr = QS   + (size_t)row*DH;
    const float* cv = CVEC + bh*DH;
    float n2 = 0.f, cq = 0.f;
    #pragma unroll
    for (int d = lane; d < DH; d += 32) {
        float qv = qr[d];
        n2 += qv*qv;
        cq += qv*cv[d];
    }
    #pragma unroll
    for (int o = 16; o > 0; o >>= 1) {
        n2 += __shfl_xor_sync(0xffffffffu, n2, o);
        cq += __shfl_xor_sync(0xffffffffu, cq, o);
    }
    if (lane == 0) { QN2[row] = fmaxf(n2, EPSF); CQg[row] = cq; }
}

// ============================================================
// logits = (Q K^T) * rsqrt(64*qn2_row), written into attn area of d_out
// grid(16,16,BH) block 256
// ============================================================
__global__ void logits_kernel(float* __restrict__ attn)
{
    int bh = blockIdx.z;
    const float* Q = QS + (size_t)bh*SQ*DH;
    const float* K = KS + (size_t)bh*SQ*DH;
    __shared__ float As[16][65];
    __shared__ float Bs[16][65];
    int tid = threadIdx.x;
    int m0 = blockIdx.y*64, n0 = blockIdx.x*64;
    int tm = (tid>>4)<<2, tn = (tid&15)<<2;
    float acc[4][4] = {};
    int lr = tid>>2, lk = (tid&3)<<2;
    const float* arow = Q + (size_t)(m0 + lr)*DH;
    const float* brow = K + (size_t)(n0 + lr)*DH;

    #pragma unroll
    for (int kt = 0; kt < DH; kt += 16) {
        float4 av = *(const float4*)(arow + kt + lk);
        float4 bv = *(const float4*)(brow + kt + lk);
        As[lk+0][lr]=av.x; As[lk+1][lr]=av.y; As[lk+2][lr]=av.z; As[lk+3][lr]=av.w;
        Bs[lk+0][lr]=bv.x; Bs[lk+1][lr]=bv.y; Bs[lk+2][lr]=bv.z; Bs[lk+3][lr]=bv.w;
        __syncthreads();
        #pragma unroll
        for (int k = 0; k < 16; k++) {
            float a[4], b[4];
            #pragma unroll
            for (int p = 0; p < 4; p++) { a[p] = As[k][tm+p]; b[p] = Bs[k][tn+p]; }
            #pragma unroll
            for (int p = 0; p < 4; p++)
                #pragma unroll
                for (int q = 0; q < 4; q++) acc[p][q] += a[p]*b[q];
        }
        __syncthreads();
    }
    #pragma unroll
    for (int p = 0; p < 4; p++) {
        int i = m0 + tm + p;
        float sc = rsqrtf(64.0f * QN2[(size_t)bh*SQ + i]);
        #pragma unroll
        for (int q = 0; q < 4; q++) {
            attn[((size_t)bh*SQ + i)*SQ + n0 + tn + q] = acc[p][q]*sc;
        }
    }
}

// ============================================================
// dual softmax per row: attn (overwrite logits in d_out) + attn_c2o (AC2O)
// grid BH*SQ, block 256 (4 elems/thread)
// ============================================================
__global__ void softmax_kernel(float* __restrict__ attn)
{
    int row = blockIdx.x;
    int bh  = row >> 10;
    float* lrow = attn + (size_t)row*SQ;
    float* orow = AC2O + (size_t)row*SQ;
    int tid = threadIdx.x;
    __shared__ float red[256];

    float l[4], cq[4];
    #pragma unroll
    for (int p = 0; p < 4; p++) {
        int j = tid + p*256;
        l[p]  = lrow[j];
        cq[p] = CQg[(size_t)bh*SQ + j];
    }

    // --- softmax 1: attn ---
    float m = fmaxf(fmaxf(l[0],l[1]), fmaxf(l[2],l[3]));
    red[tid] = m; __syncthreads();
    #pragma unroll
    for (int o = 128; o > 0; o >>= 1) { if (tid < o) red[tid] = fmaxf(red[tid], red[tid+o]); __syncthreads(); }
    m = red[0]; __syncthreads();
    float e1[4], s1 = 0.f;
    #pragma unroll
    for (int p = 0; p < 4; p++) { e1[p] = __expf(l[p] - m); s1 += e1[p]; }
    red[tid] = s1; __syncthreads();
    #pragma unroll
    for (int o = 128; o > 0; o >>= 1) { if (tid < o) red[tid] += red[tid+o]; __syncthreads(); }
    float inv1 = 1.0f / red[0]; __syncthreads();

    // --- softmax 2: c2o ---
    float r = rsqrtf(QN2[row] * CN2[bh]);
    float l2[4];
    #pragma unroll
    for (int p = 0; p < 4; p++) l2[p] = l[p]*cq[p]*r;
    float m2 = fmaxf(fmaxf(l2[0],l2[1]), fmaxf(l2[2],l2[3]));
    red[tid] = m2; __syncthreads();
    #pragma unroll
    for (int o = 128; o > 0; o >>= 1) { if (tid < o) red[tid] = fmaxf(red[tid], red[tid+o]); __syncthreads(); }
    m2 = red[0]; __syncthreads();
    float e2[4], s2 = 0.f;
    #pragma unroll
    for (int p = 0; p < 4; p++) { e2[p] = __expf(l2[p] - m2); s2 += e2[p]; }
    red[tid] = s2; __syncthreads();
    #pragma unroll
    for (int o = 128; o > 0; o >>= 1) { if (tid < o) red[tid] += red[tid+o]; __syncthreads(); }
    float inv2 = 1.0f / red[0];

    #pragma unroll
    for (int p = 0; p < 4; p++) {
        int j = tid + p*256;
        lrow[j] = e1[p]*inv1;
        orow[j] = e2[p]*inv2;
    }
}

// ============================================================
// values = attn @ V + attn_c2o @ CP  -> VALS (token rows 1..1024)
// grid(1,16,BH) block 256
// ============================================================
__global__ void values_kernel(const float* __restrict__ attn)
{
    int bh = blockIdx.z;
    int m0 = blockIdx.y*64;
    const float* A1 = attn + (size_t)bh*SQ*SQ;
    const float* A2 = AC2O + (size_t)bh*SQ*SQ;
    const float* B1 = VS  + (size_t)bh*SQ*DH;
    const float* B2 = CPS + (size_t)bh*SQ*DH;

    __shared__ float As1[16][65], As2[16][65];
    __shared__ float Bs1[16][64], Bs2[16][64];
    int tid = threadIdx.x;
    int tm = (tid>>4)<<2, tn = (tid&15)<<2;
    float acc[4][4] = {};
    int lr = tid>>2, lk = (tid&3)<<2;          // A load
    int bk = tid>>4, bn = (tid&15)<<2;         // B load

    for (int kt = 0; kt < SQ; kt += 16) {
        float4 a1 = *(const float4*)(A1 + (size_t)(m0+lr)*SQ + kt + lk);
        float4 a2 = *(const float4*)(A2 + (size_t)(m0+lr)*SQ + kt + lk);
        As1[lk+0][lr]=a1.x; As1[lk+1][lr]=a1.y; As1[lk+2][lr]=a1.z; As1[lk+3][lr]=a1.w;
        As2[lk+0][lr]=a2.x; As2[lk+1][lr]=a2.y; As2[lk+2][lr]=a2.z; As2[lk+3][lr]=a2.w;
        *(float4*)&Bs1[bk][bn] = *(const float4*)(B1 + (size_t)(kt+bk)*DH + bn);
        *(float4*)&Bs2[bk][bn] = *(const float4*)(B2 + (size_t)(kt+bk)*DH + bn);
        __syncthreads();
        #pragma unroll
        for (int k = 0; k < 16; k++) {
            float a1v[4], a2v[4], b1v[4], b2v[4];
            #pragma unroll
            for (int p = 0; p < 4; p++) {
                a1v[p]=As1[k][tm+p]; a2v[p]=As2[k][tm+p];
                b1v[p]=Bs1[k][tn+p]; b2v[p]=Bs2[k][tn+p];
            }
            #pragma unroll
            for (int p = 0; p < 4; p++)
                #pragma unroll
                for (int q = 0; q < 4; q++)
                    acc[p][q] += a1v[p]*b1v[q] + a2v[p]*b2v[q];
        }
        __syncthreads();
    }
    int b_ = bh / HH, h_ = bh % HH;
    #pragma unroll
    for (int p = 0; p < 4; p++) {
        int i = m0 + tm + p;
        #pragma unroll
        for (int q = 0; q < 4; q++) {
            VALS[(size_t)(b_*SS + 1 + i)*EE + h_*DH + tn + q] = acc[p][q];
        }
    }
}

// ============================================================
// cls path: ck softmax -> cls_out (VALS token row 0). grid BH, block 256
// ============================================================
__global__ void cls_kernel()
{
    int bh = blockIdx.x;
    int tid = threadIdx.x;
    const float* Kp = KS + (size_t)bh*SQ*DH;
    const float* Vp = VS + (size_t)bh*SQ*DH;
    __shared__ float p_s[SQ];
    __shared__ float red[256];
    __shared__ float c_s[DH];
    if (tid < DH) c_s[tid] = CVEC[bh*DH + tid];
    __syncthreads();

    float scale = rsqrtf(64.0f * CN2[bh]);
    float lo[4];
    #pragma unroll
    for (int p = 0; p < 4; p++) {
        int j = tid + p*256;
        const float* kr = Kp + (size_t)j*DH;
        float s = 0.f;
        #pragma unroll
        for (int d = 0; d < DH; d += 4) {
            float4 kv = *(const float4*)(kr + d);
            s += c_s[d]*kv.x + c_s[d+1]*kv.y + c_s[d+2]*kv.z + c_s[d+3]*kv.w;
        }
        lo[p] = s * scale;
    }
    float m = fmaxf(fmaxf(lo[0],lo[1]), fmaxf(lo[2],lo[3]));
    red[tid] = m; __syncthreads();
    #pragma unroll
    for (int o = 128; o > 0; o >>= 1) { if (tid < o) red[tid] = fmaxf(red[tid], red[tid+o]); __syncthreads(); }
    m = red[0]; __syncthreads();
    float e[4], s = 0.f;
    #pragma unroll
    for (int p = 0; p < 4; p++) { e[p] = __expf(lo[p] - m); s += e[p]; }
    red[tid] = s; __syncthreads();
    #pragma unroll
    for (int o = 128; o > 0; o >>= 1) { if (tid < o) red[tid] += red[tid+o]; __syncthreads(); }
    float inv = 1.0f / red[0]; __syncthreads();
    #pragma unroll
    for (int p = 0; p < 4; p++) p_s[tid + p*256] = e[p]*inv;
    __syncthreads();

    // out[d] = sum_j p[j] * V[j,d]
    int d = tid & 63, g = tid >> 6;
    float acc = 0.f;
    for (int j = g*256; j < (g+1)*256; j++) acc += p_s[j] * Vp[(size_t)j*DH + d];
    red[tid] = acc; __syncthreads();
    if (g == 0) {
        float rsum = red[tid] + red[tid+64] + red[tid+128] + red[tid+192];
        int b_ = bh / HH, h_ = bh % HH;
        VALS[(size_t)(b_*SS)*EE + h_*DH + d] = rsum;
    }
}

// ============================================================
// out = VALS @ Wo^T + bo. M=4100 (guarded). grid(16,65) block 256
// ============================================================
__global__ void out_kernel(const float* __restrict__ Wo,
                           const float* __restrict__ bo,
                           float* __restrict__ out)
{
    __shared__ float As[16][65];
    __shared__ float Bs[16][65];
    int tid = threadIdx.x;
    int m0 = blockIdx.y*64, n0 = blockIdx.x*64;
    int tm = (tid>>4)<<2, tn = (tid&15)<<2;
    float acc[4][4] = {};
    int lr = tid>>2, lk = (tid&3)<<2;
    int mrow = m0 + lr;
    bool mval = (mrow < BB*SS);
    const float* arow = VALS + (size_t)(mval ? mrow : 0)*EE;
    const float* brow = Wo   + (size_t)(n0 + lr)*EE;

    for (int kt = 0; kt < EE; kt += 16) {
        float4 av = mval ? *(const float4*)(arow + kt + lk) : make_float4(0.f,0.f,0.f,0.f);
        float4 bv = *(const float4*)(brow + kt + lk);
        As[lk+0][lr]=av.x; As[lk+1][lr]=av.y; As[lk+2][lr]=av.z; As[lk+3][lr]=av.w;
        Bs[lk+0][lr]=bv.x; Bs[lk+1][lr]=bv.y; Bs[lk+2][lr]=bv.z; Bs[lk+3][lr]=bv.w;
        __syncthreads();
        #pragma unroll
        for (int k = 0; k < 16; k++) {
            float a[4], b[4];
            #pragma unroll
            for (int p = 0; p < 4; p++) { a[p] = As[k][tm+p]; b[p] = Bs[k][tn+p]; }
            #pragma unroll
            for (int p = 0; p < 4; p++)
                #pragma unroll
                for (int q = 0; q < 4; q++) acc[p][q] += a[p]*b[q];
        }
        __syncthreads();
    }
    #pragma unroll
    for (int p = 0; p < 4; p++) {
        int mr = m0 + tm + p;
        if (mr >= BB*SS) continue;
        #pragma unroll
        for (int q = 0; q < 4; q++) {
            int j = n0 + tn + q;
            out[(size_t)mr*EE + j] = acc[p][q] + bo[j];
        }
    }
}

extern "C" void kernel_launch(void* const* d_in, const int* in_sizes, int n_in,
                              void* d_out, int out_size)
{
    const float* x  = (const float*)d_in[0];
    const float* Wq = (const float*)d_in[1];
    const float* bq = (const float*)d_in[2];
    const float* Wk = (const float*)d_in[3];
    const float* bk = (const float*)d_in[4];
    const float* Wv = (const float*)d_in[5];
    const float* bv = (const float*)d_in[6];
    const float* Wo = (const float*)d_in[7];
    const float* bo = (const float*)d_in[8];
    const float* Wc = (const float*)d_in[9];
    const float* bc = (const float*)d_in[10];

    float* out  = (float*)d_out;
    float* attn = out + (size_t)BB*SS*EE;

    proj_kernel<<<dim3(16,64,4), 256>>>(x, Wq,bq, Wk,bk, Wv,bv, Wc,bc);
    clsproj_kernel<<<BH, 64>>>(x, Wq, bq);
    qstats_kernel<<<BH*SQ/8, 256>>>();
    logits_kernel<<<dim3(16,16,BH), 256>>>(attn);
    softmax_kernel<<<BH*SQ, 256>>>(attn);
    values_kernel<<<dim3(1,16,BH), 256>>>(attn);
    cls_kernel<<<BH, 256>>>();
    out_kernel<<<dim3(16,65), 256>>>(Wo, bo, out);
}

// round 2
// speedup vs baseline: 1.3516x; 1.3516x over previous
#include <cuda_runtime.h>

#define BB 4
#define SS 1025
#define SQ 1024
#define EE 1024
#define HH 16
#define DH 64
#define BH (BB*HH)
#define EPSF 1e-5f

// ---- scratch (allocation-free: device globals) ----
__device__ float QS[BH*SQ*DH];     // 16 MB
__device__ float KS[BH*SQ*DH];
__device__ float VS[BH*SQ*DH];
__device__ float CPS[BH*SQ*DH];    // cls_proj heads
__device__ float AC2O[(size_t)BH*SQ*SQ];  // 256 MB attn_c2o
__device__ float VALS[BB*SS*EE];   // pre-output values (cls row 0 + tokens)
__device__ float CVEC[BH*DH];      // c vector per (b,h)
__device__ float CN2[BH];          // clipped |c|^2
__device__ float QN2[BH*SQ];       // clipped |q|^2 per row
__device__ float CQg[BH*SQ];       // c . q_j per key j

// ============================================================
// Projection GEMM: 128x128 tile, 8x8 micro (split fragments),
// double-buffered kt=8. grid(8, 32, 4) block 256.
// out[token, j] = xt[token,:] . W[j,:] + b[j], scattered to heads
// ============================================================
__global__ void proj_kernel(const float* __restrict__ x,
                            const float* __restrict__ W0, const float* __restrict__ b0,
                            const float* __restrict__ W1, const float* __restrict__ b1,
                            const float* __restrict__ W2, const float* __restrict__ b2,
                            const float* __restrict__ W3, const float* __restrict__ b3)
{
    int w = blockIdx.z;
    const float* Wm   = (w==0)?W0:(w==1)?W1:(w==2)?W2:W3;
    const float* bias = (w==0)?b0:(w==1)?b1:(w==2)?b2:b3;
    float* dst        = (w==0)?QS:(w==1)?KS:(w==2)?VS:CPS;

    __shared__ float As[2][8][132];
    __shared__ float Bs[2][8][132];
    int tid = threadIdx.x;
    int m0 = blockIdx.y*128, n0 = blockIdx.x*128;
    int rm4 = (tid>>4)<<2, rn4 = (tid&15)<<2;
    int lr = tid>>1, lc = (tid&1)<<2;

    int t  = m0 + lr;
    int b_ = t >> 10, i_ = t & 1023;
    const float* arow = x  + (size_t)(b_*SS + i_ + 1)*EE + lc;  // xt row (skip cls)
    const float* brow = Wm + (size_t)(n0 + lr)*EE + lc;

    float acc[8][8] = {};
    float4 av = *(const float4*)arow;
    float4 bv = *(const float4*)brow;
    int buf = 0;

    #pragma unroll 1
    for (int kt = 0; kt < EE; kt += 8) {
        As[buf][lc+0][lr]=av.x; As[buf][lc+1][lr]=av.y; As[buf][lc+2][lr]=av.z; As[buf][lc+3][lr]=av.w;
        Bs[buf][lc+0][lr]=bv.x; Bs[buf][lc+1][lr]=bv.y; Bs[buf][lc+2][lr]=bv.z; Bs[buf][lc+3][lr]=bv.w;
        __syncthreads();
        if (kt + 8 < EE) {
            av = *(const float4*)(arow + kt + 8);
            bv = *(const float4*)(brow + kt + 8);
        }
        #pragma unroll
        for (int k = 0; k < 8; k++) {
            float a[8], b[8];
            *(float4*)&a[0] = *(const float4*)&As[buf][k][rm4];
            *(float4*)&a[4] = *(const float4*)&As[buf][k][rm4+64];
            *(float4*)&b[0] = *(const float4*)&Bs[buf][k][rn4];
            *(float4*)&b[4] = *(const float4*)&Bs[buf][k][rn4+64];
            #pragma unroll
            for (int i = 0; i < 8; i++)
                #pragma unroll
                for (int j = 0; j < 8; j++) acc[i][j] += a[i]*b[j];
        }
        buf ^= 1;
    }

    #pragma unroll
    for (int i = 0; i < 8; i++) {
        int tok = m0 + rm4 + (i&3) + ((i>>2)<<6);
        int bb2 = tok >> 10, ii2 = tok & 1023;
        #pragma unroll
        for (int j = 0; j < 8; j++) {
            int c = n0 + rn4 + (j&3) + ((j>>2)<<6);
            int h2 = c >> 6, d2 = c & 63;
            dst[(size_t)((bb2*HH + h2)*SQ + ii2)*DH + d2] = acc[i][j] + bias[c];
        }
    }
}

// ============================================================
// cls token projection: c[bh][d] = x[b,0,:] . Wq[h*64+d,:] + bq, plus CN2
// grid BH, block 64
// ============================================================
__global__ void clsproj_kernel(const float* __restrict__ x,
                               const float* __restrict__ Wq,
                               const float* __restrict__ bq)
{
    int bh = blockIdx.x;
    int b_ = bh / HH, h_ = bh % HH;
    int d  = threadIdx.x;
    int j  = h_*DH + d;
    const float* xr = x  + (size_t)(b_*SS)*EE;
    const float* wr = Wq + (size_t)j*EE;
    float s = 0.f;
    for (int e = 0; e < EE; e += 4) {
        float4 xv = *(const float4*)(xr + e);
        float4 wv = *(const float4*)(wr + e);
        s += xv.x*wv.x + xv.y*wv.y + xv.z*wv.z + xv.w*wv.w;
    }
    s += bq[j];
    CVEC[bh*DH + d] = s;
    __shared__ float red[64];
    red[d] = s*s; __syncthreads();
    for (int o = 32; o > 0; o >>= 1) { if (d < o) red[d] += red[d+o]; __syncthreads(); }
    if (d == 0) CN2[bh] = fmaxf(red[0], EPSF);
}

// ============================================================
// per-row q stats: QN2 (clipped) and CQ = c.q. grid BH*SQ/8, block 256
// ============================================================
__global__ void qstats_kernel()
{
    int row  = blockIdx.x*8 + (threadIdx.x >> 5);
    int lane = threadIdx.x & 31;
    int bh   = row >> 10;
    const float* qr = QS   + (size_t)row*DH;
    const float* cv = CVEC + bh*DH;
    float n2 = 0.f, cq = 0.f;
    #pragma unroll
    for (int d = lane; d < DH; d += 32) {
        float qv = qr[d];
        n2 += qv*qv;
        cq += qv*cv[d];
    }
    #pragma unroll
    for (int o = 16; o > 0; o >>= 1) {
        n2 += __shfl_xor_sync(0xffffffffu, n2, o);
        cq += __shfl_xor_sync(0xffffffffu, cq, o);
    }
    if (lane == 0) { QN2[row] = fmaxf(n2, EPSF); CQg[row] = cq; }
}

// ============================================================
// logits = (Q K^T) * rsqrt(64*qn2_row). 128x128 tile, 8x8 micro,
// K=64 in two kt=32 passes. grid(8,8,BH) block 256
// ============================================================
__global__ void logits_kernel(float* __restrict__ attn)
{
    int bh = blockIdx.z;
    const float* Q = QS + (size_t)bh*SQ*DH;
    const float* K = KS + (size_t)bh*SQ*DH;
    __shared__ float As[32][132];
    __shared__ float Bs[32][132];
    int tid = threadIdx.x;
    int m0 = blockIdx.y*128, n0 = blockIdx.x*128;
    int rm4 = (tid>>4)<<2, rn4 = (tid&15)<<2;
    int lr = tid>>1;
    int lc0 = (tid&1)<<4;
    float acc[8][8] = {};

    #pragma unroll
    for (int kt = 0; kt < DH; kt += 32) {
        #pragma unroll
        for (int t4 = 0; t4 < 4; t4++) {
            int kk = lc0 + t4*4;
            float4 v = *(const float4*)(Q + (size_t)(m0+lr)*DH + kt + kk);
            As[kk+0][lr]=v.x; As[kk+1][lr]=v.y; As[kk+2][lr]=v.z; As[kk+3][lr]=v.w;
            float4 u = *(const float4*)(K + (size_t)(n0+lr)*DH + kt + kk);
            Bs[kk+0][lr]=u.x; Bs[kk+1][lr]=u.y; Bs[kk+2][lr]=u.z; Bs[kk+3][lr]=u.w;
        }
        __syncthreads();
        #pragma unroll
        for (int k = 0; k < 32; k++) {
            float a[8], b[8];
            *(float4*)&a[0] = *(const float4*)&As[k][rm4];
            *(float4*)&a[4] = *(const float4*)&As[k][rm4+64];
            *(float4*)&b[0] = *(const float4*)&Bs[k][rn4];
            *(float4*)&b[4] = *(const float4*)&Bs[k][rn4+64];
            #pragma unroll
            for (int i = 0; i < 8; i++)
                #pragma unroll
                for (int j = 0; j < 8; j++) acc[i][j] += a[i]*b[j];
        }
        __syncthreads();
    }
    #pragma unroll
    for (int i = 0; i < 8; i++) {
        int r = m0 + rm4 + (i&3) + ((i>>2)<<6);
        float sc = rsqrtf(64.0f * QN2[(size_t)bh*SQ + r]);
        #pragma unroll
        for (int j = 0; j < 8; j++) {
            int c = n0 + rn4 + (j&3) + ((j>>2)<<6);
            attn[((size_t)bh*SQ + r)*SQ + c] = acc[i][j]*sc;
        }
    }
}

// ============================================================
// dual softmax per row: attn (in place) + attn_c2o (AC2O)
// grid BH*SQ, block 256
// ============================================================
__global__ void softmax_kernel(float* __restrict__ attn)
{
    int row = blockIdx.x;
    int bh  = row >> 10;
    float* lrow = attn + (size_t)row*SQ;
    float* orow = AC2O + (size_t)row*SQ;
    int tid = threadIdx.x;
    __shared__ float red[256];

    float l[4], cq[4];
    #pragma unroll
    for (int p = 0; p < 4; p++) {
        int j = tid + p*256;
        l[p]  = lrow[j];
        cq[p] = CQg[(size_t)bh*SQ + j];
    }

    float m = fmaxf(fmaxf(l[0],l[1]), fmaxf(l[2],l[3]));
    red[tid] = m; __syncthreads();
    #pragma unroll
    for (int o = 128; o > 0; o >>= 1) { if (tid < o) red[tid] = fmaxf(red[tid], red[tid+o]); __syncthreads(); }
    m = red[0]; __syncthreads();
    float e1[4], s1 = 0.f;
    #pragma unroll
    for (int p = 0; p < 4; p++) { e1[p] = __expf(l[p] - m); s1 += e1[p]; }
    red[tid] = s1; __syncthreads();
    #pragma unroll
    for (int o = 128; o > 0; o >>= 1) { if (tid < o) red[tid] += red[tid+o]; __syncthreads(); }
    float inv1 = 1.0f / red[0]; __syncthreads();

    float r = rsqrtf(QN2[row] * CN2[bh]);
    float l2[4];
    #pragma unroll
    for (int p = 0; p < 4; p++) l2[p] = l[p]*cq[p]*r;
    float m2 = fmaxf(fmaxf(l2[0],l2[1]), fmaxf(l2[2],l2[3]));
    red[tid] = m2; __syncthreads();
    #pragma unroll
    for (int o = 128; o > 0; o >>= 1) { if (tid < o) red[tid] = fmaxf(red[tid], red[tid+o]); __syncthreads(); }
    m2 = red[0]; __syncthreads();
    float e2[4], s2 = 0.f;
    #pragma unroll
    for (int p = 0; p < 4; p++) { e2[p] = __expf(l2[p] - m2); s2 += e2[p]; }
    red[tid] = s2; __syncthreads();
    #pragma unroll
    for (int o = 128; o > 0; o >>= 1) { if (tid < o) red[tid] += red[tid+o]; __syncthreads(); }
    float inv2 = 1.0f / red[0];

    #pragma unroll
    for (int p = 0; p < 4; p++) {
        int j = tid + p*256;
        lrow[j] = e1[p]*inv1;
        orow[j] = e2[p]*inv2;
    }
}

// ============================================================
// values = attn @ V + attn_c2o @ CP -> VALS (token rows 1..1024)
// 256x64 tile, 16x4 micro, double-buffered kt=8. grid(4,BH) block 256
// ============================================================
__global__ void values_kernel(const float* __restrict__ attn)
{
    int bh = blockIdx.y;
    int m0 = blockIdx.x*256;
    const float* A1 = attn + (size_t)bh*SQ*SQ;
    const float* A2 = AC2O + (size_t)bh*SQ*SQ;
    const float* B1 = VS  + (size_t)bh*SQ*DH;
    const float* B2 = CPS + (size_t)bh*SQ*DH;

    __shared__ float As1[2][8][260], As2[2][8][260];
    __shared__ float Bs1[2][8][68],  Bs2[2][8][68];
    int tid = threadIdx.x;
    int rm4 = (tid>>4)<<2, rn4 = (tid&15)<<2;

    const float* a1row = A1 + (size_t)(m0 + tid)*SQ;
    const float* a2row = A2 + (size_t)(m0 + tid)*SQ;
    int bk = tid>>4, bn = (tid&15)<<2;   // B loads (tid<128 only)

    float acc[16][4] = {};
    float4 a1v0 = *(const float4*)(a1row);
    float4 a1v1 = *(const float4*)(a1row + 4);
    float4 a2v0 = *(const float4*)(a2row);
    float4 a2v1 = *(const float4*)(a2row + 4);
    float4 b1v = make_float4(0,0,0,0), b2v = make_float4(0,0,0,0);
    if (tid < 128) {
        b1v = *(const float4*)(B1 + (size_t)bk*DH + bn);
        b2v = *(const float4*)(B2 + (size_t)bk*DH + bn);
    }
    int buf = 0;

    #pragma unroll 1
    for (int kt = 0; kt < SQ; kt += 8) {
        As1[buf][0][tid]=a1v0.x; As1[buf][1][tid]=a1v0.y; As1[buf][2][tid]=a1v0.z; As1[buf][3][tid]=a1v0.w;
        As1[buf][4][tid]=a1v1.x; As1[buf][5][tid]=a1v1.y; As1[buf][6][tid]=a1v1.z; As1[buf][7][tid]=a1v1.w;
        As2[buf][0][tid]=a2v0.x; As2[buf][1][tid]=a2v0.y; As2[buf][2][tid]=a2v0.z; As2[buf][3][tid]=a2v0.w;
        As2[buf][4][tid]=a2v1.x; As2[buf][5][tid]=a2v1.y; As2[buf][6][tid]=a2v1.z; As2[buf][7][tid]=a2v1.w;
        if (tid < 128) {
            *(float4*)&Bs1[buf][bk][bn] = b1v;
            *(float4*)&Bs2[buf][bk][bn] = b2v;
        }
        __syncthreads();
        if (kt + 8 < SQ) {
            a1v0 = *(const float4*)(a1row + kt + 8);
            a1v1 = *(const float4*)(a1row + kt + 12);
            a2v0 = *(const float4*)(a2row + kt + 8);
            a2v1 = *(const float4*)(a2row + kt + 12);
            if (tid < 128) {
                b1v = *(const float4*)(B1 + (size_t)(kt + 8 + bk)*DH + bn);
                b2v = *(const float4*)(B2 + (size_t)(kt + 8 + bk)*DH + bn);
            }
        }
        #pragma unroll
        for (int k = 0; k < 8; k++) {
            float a1[16], a2[16], b1[4], b2[4];
            *(float4*)&a1[0]  = *(const float4*)&As1[buf][k][rm4];
            *(float4*)&a1[4]  = *(const float4*)&As1[buf][k][rm4+64];
            *(float4*)&a1[8]  = *(const float4*)&As1[buf][k][rm4+128];
            *(float4*)&a1[12] = *(const float4*)&As1[buf][k][rm4+192];
            *(float4*)&a2[0]  = *(const float4*)&As2[buf][k][rm4];
            *(float4*)&a2[4]  = *(const float4*)&As2[buf][k][rm4+64];
            *(float4*)&a2[8]  = *(const float4*)&As2[buf][k][rm4+128];
            *(float4*)&a2[12] = *(const float4*)&As2[buf][k][rm4+192];
            *(float4*)&b1[0]  = *(const float4*)&Bs1[buf][k][rn4];
            *(float4*)&b2[0]  = *(const float4*)&Bs2[buf][k][rn4];
            #pragma unroll
            for (int i = 0; i < 16; i++)
                #pragma unroll
                for (int j = 0; j < 4; j++)
                    acc[i][j] += a1[i]*b1[j] + a2[i]*b2[j];
        }
        buf ^= 1;
    }
    int b_ = bh / HH, h_ = bh % HH;
    #pragma unroll
    for (int i = 0; i < 16; i++) {
        int r = m0 + rm4 + (i&3) + ((i>>2)<<6);
        #pragma unroll
        for (int j = 0; j < 4; j++) {
            VALS[(size_t)(b_*SS + 1 + r)*EE + h_*DH + rn4 + j] = acc[i][j];
        }
    }
}

// ============================================================
// cls path: ck softmax -> cls_out (VALS token row 0). grid BH, block 256
// ============================================================
__global__ void cls_kernel()
{
    int bh = blockIdx.x;
    int tid = threadIdx.x;
    const float* Kp = KS + (size_t)bh*SQ*DH;
    const float* Vp = VS + (size_t)bh*SQ*DH;
    __shared__ float p_s[SQ];
    __shared__ float red[256];
    __shared__ float c_s[DH];
    if (tid < DH) c_s[tid] = CVEC[bh*DH + tid];
    __syncthreads();

    float scale = rsqrtf(64.0f * CN2[bh]);
    float lo[4];
    #pragma unroll
    for (int p = 0; p < 4; p++) {
        int j = tid + p*256;
        const float* kr = Kp + (size_t)j*DH;
        float s = 0.f;
        #pragma unroll
        for (int d = 0; d < DH; d += 4) {
            float4 kv = *(const float4*)(kr + d);
            s += c_s[d]*kv.x + c_s[d+1]*kv.y + c_s[d+2]*kv.z + c_s[d+3]*kv.w;
        }
        lo[p] = s * scale;
    }
    float m = fmaxf(fmaxf(lo[0],lo[1]), fmaxf(lo[2],lo[3]));
    red[tid] = m; __syncthreads();
    #pragma unroll
    for (int o = 128; o > 0; o >>= 1) { if (tid < o) red[tid] = fmaxf(red[tid], red[tid+o]); __syncthreads(); }
    m = red[0]; __syncthreads();
    float e[4], s = 0.f;
    #pragma unroll
    for (int p = 0; p < 4; p++) { e[p] = __expf(lo[p] - m); s += e[p]; }
    red[tid] = s; __syncthreads();
    #pragma unroll
    for (int o = 128; o > 0; o >>= 1) { if (tid < o) red[tid] += red[tid+o]; __syncthreads(); }
    float inv = 1.0f / red[0]; __syncthreads();
    #pragma unroll
    for (int p = 0; p < 4; p++) p_s[tid + p*256] = e[p]*inv;
    __syncthreads();

    int d = tid & 63, g = tid >> 6;
    float acc = 0.f;
    for (int j = g*256; j < (g+1)*256; j++) acc += p_s[j] * Vp[(size_t)j*DH + d];
    red[tid] = acc; __syncthreads();
    if (g == 0) {
        float rsum = red[tid] + red[tid+64] + red[tid+128] + red[tid+192];
        int b_ = bh / HH, h_ = bh % HH;
        VALS[(size_t)(b_*SS)*EE + h_*DH + d] = rsum;
    }
}

// ============================================================
// out = VALS @ Wo^T + bo. 128x128 tile, 8x8 micro, double buffer.
// M=4100 guarded. grid(8,33) block 256
// ============================================================
__global__ void out_kernel(const float* __restrict__ Wo,
                           const float* __restrict__ bo,
                           float* __restrict__ out)
{
    __shared__ float As[2][8][132];
    __shared__ float Bs[2][8][132];
    int tid = threadIdx.x;
    int m0 = blockIdx.y*128, n0 = blockIdx.x*128;
    int rm4 = (tid>>4)<<2, rn4 = (tid&15)<<2;
    int lr = tid>>1, lc = (tid&1)<<2;

    int mrow = m0 + lr;
    int msafe = (mrow < BB*SS) ? mrow : (BB*SS - 1);
    const float* arow = VALS + (size_t)msafe*EE + lc;
    const float* brow = Wo   + (size_t)(n0 + lr)*EE + lc;

    float acc[8][8] = {};
    float4 av = *(const float4*)arow;
    float4 bv = *(const float4*)brow;
    int buf = 0;

    #pragma unroll 1
    for (int kt = 0; kt < EE; kt += 8) {
        As[buf][lc+0][lr]=av.x; As[buf][lc+1][lr]=av.y; As[buf][lc+2][lr]=av.z; As[buf][lc+3][lr]=av.w;
        Bs[buf][lc+0][lr]=bv.x; Bs[buf][lc+1][lr]=bv.y; Bs[buf][lc+2][lr]=bv.z; Bs[buf][lc+3][lr]=bv.w;
        __syncthreads();
        if (kt + 8 < EE) {
            av = *(const float4*)(arow + kt + 8);
            bv = *(const float4*)(brow + kt + 8);
        }
        #pragma unroll
        for (int k = 0; k < 8; k++) {
            float a[8], b[8];
            *(float4*)&a[0] = *(const float4*)&As[buf][k][rm4];
            *(float4*)&a[4] = *(const float4*)&As[buf][k][rm4+64];
            *(float4*)&b[0] = *(const float4*)&Bs[buf][k][rn4];
            *(float4*)&b[4] = *(const float4*)&Bs[buf][k][rn4+64];
            #pragma unroll
            for (int i = 0; i < 8; i++)
                #pragma unroll
                for (int j = 0; j < 8; j++) acc[i][j] += a[i]*b[j];
        }
        buf ^= 1;
    }
    #pragma unroll
    for (int i = 0; i < 8; i++) {
        int mr = m0 + rm4 + (i&3) + ((i>>2)<<6);
        if (mr >= BB*SS) continue;
        #pragma unroll
        for (int j = 0; j < 8; j++) {
            int c = n0 + rn4 + (j&3) + ((j>>2)<<6);
            out[(size_t)mr*EE + c] = acc[i][j] + bo[c];
        }
    }
}

extern "C" void kernel_launch(void* const* d_in, const int* in_sizes, int n_in,
                              void* d_out, int out_size)
{
    const float* x  = (const float*)d_in[0];
    const float* Wq = (const float*)d_in[1];
    const float* bq = (const float*)d_in[2];
    const float* Wk = (const float*)d_in[3];
    const float* bk = (const float*)d_in[4];
    const float* Wv = (const float*)d_in[5];
    const float* bv = (const float*)d_in[6];
    const float* Wo = (const float*)d_in[7];
    const float* bo = (const float*)d_in[8];
    const float* Wc = (const float*)d_in[9];
    const float* bc = (const float*)d_in[10];

    float* out  = (float*)d_out;
    float* attn = out + (size_t)BB*SS*EE;

    proj_kernel<<<dim3(8,32,4), 256>>>(x, Wq,bq, Wk,bk, Wv,bv, Wc,bc);
    clsproj_kernel<<<BH, 64>>>(x, Wq, bq);
    qstats_kernel<<<BH*SQ/8, 256>>>();
    logits_kernel<<<dim3(8,8,BH), 256>>>(attn);
    softmax_kernel<<<BH*SQ, 256>>>(attn);
    values_kernel<<<dim3(4,BH), 256>>>(attn);
    cls_kernel<<<BH, 256>>>();
    out_kernel<<<dim3(8,33), 256>>>(Wo, bo, out);
}

// round 5
// speedup vs baseline: 2.6345x; 1.9492x over previous
#include <cuda_runtime.h>
#include <cuda_bf16.h>
#include <cstdint>

#define BB 4
#define SS 1025
#define SQ 1024
#define EE 1024
#define HH 16
#define DH 64
#define BH (BB*HH)
#define EPSF 1e-5f
#define MROWS_OUT (BB*SS)     // 4100
#define MTILES_OUT 33         // 33*128 = 4224

typedef __nv_bfloat16 bf16;

// ---------------- device scratch (allocation-free) ----------------
__device__ float QS[BH*SQ*DH];          // fp32 q  (qstats)
__device__ float KS[BH*SQ*DH];          // fp32 k  (cls path)
__device__ float VS[BH*SQ*DH];          // fp32 v  (cls path)
__device__ bf16 XH[BB*SS*EE],  XL[BB*SS*EE];
__device__ bf16 WqH[EE*EE], WqL[EE*EE], WkH[EE*EE], WkL[EE*EE];
__device__ bf16 WvH[EE*EE], WvL[EE*EE], WcH[EE*EE], WcL[EE*EE];
__device__ bf16 WoH[EE*EE], WoL[EE*EE];
__device__ bf16 QH[BH*SQ*DH], QL[BH*SQ*DH], KH[BH*SQ*DH], KL[BH*SQ*DH];
__device__ bf16 VTH[BH*DH*SQ], VTL[BH*DH*SQ];        // V^T [bh][d][j]
__device__ bf16 CPTH[BH*DH*SQ], CPTL[BH*DH*SQ];      // cls_proj^T
__device__ bf16 ATH[(size_t)BH*SQ*SQ], ATL[(size_t)BH*SQ*SQ];   // attn hi/lo
__device__ bf16 ACH[(size_t)BH*SQ*SQ], ACL[(size_t)BH*SQ*SQ];   // attn_c2o hi/lo
__device__ bf16 VALSH[(size_t)MTILES_OUT*128*EE], VALSL[(size_t)MTILES_OUT*128*EE];
__device__ float CVEC[BH*DH];
__device__ float CN2[BH];
__device__ float QN2[BH*SQ];
__device__ float CQg[BH*SQ];

// ---------------- warp-mma helpers (compute_100-safe) ----------------
__device__ __forceinline__ uint32_t s2u(const void* p) {
    uint32_t a;
    asm("{ .reg .u64 t; cvta.to.shared.u64 t, %1; cvt.u32.u64 %0, t; }" : "=r"(a) : "l"(p));
    return a;
}
#define LDSM4(R0,R1,R2,R3,addr) \
    asm volatile("ldmatrix.sync.aligned.m8n8.x4.shared.b16 {%0,%1,%2,%3}, [%4];" \
        : "=r"(R0),"=r"(R1),"=r"(R2),"=r"(R3) : "r"(addr))

__device__ __forceinline__ void mma16816(float* c, uint32_t a0, uint32_t a1,
                                         uint32_t a2, uint32_t a3,
                                         uint32_t b0, uint32_t b1) {
    asm volatile(
        "mma.sync.aligned.m16n8k16.row.col.f32.bf16.bf16.f32 "
        "{%0,%1,%2,%3}, {%4,%5,%6,%7}, {%8,%9}, {%0,%1,%2,%3};"
        : "+f"(c[0]), "+f"(c[1]), "+f"(c[2]), "+f"(c[3])
        : "r"(a0), "r"(a1), "r"(a2), "r"(a3), "r"(b0), "r"(b1));
}

// one k16 step over a warp tile of MT*16 x 32 (4 n8-tiles), split-bf16 3-pass
template<int MT>
__device__ __forceinline__ void wmma_step(float (*acc)[4][4],
    uint32_t aHb, uint32_t aLb, uint32_t bHb, uint32_t bLb,
    int mrow0, int ncol0, int k0, int lane)
{
    uint32_t aH[MT][4], aL[MT][4];
    #pragma unroll
    for (int mi = 0; mi < MT; mi++) {
        uint32_t off = ((uint32_t)(mrow0 + mi*16 + (lane & 15))*40u + (uint32_t)k0 + ((lane >> 4) << 3)) * 2u;
        LDSM4(aH[mi][0], aH[mi][1], aH[mi][2], aH[mi][3], aHb + off);
        LDSM4(aL[mi][0], aL[mi][1], aL[mi][2], aL[mi][3], aLb + off);
    }
    uint32_t bHf[4][2], bLf[4][2];
    int j = lane >> 3;
    #pragma unroll
    for (int p = 0; p < 2; p++) {
        uint32_t off = ((uint32_t)(ncol0 + p*16 + ((j >> 1) << 3) + (lane & 7))*40u + (uint32_t)k0 + ((j & 1) << 3)) * 2u;
        uint32_t r0, r1, r2, r3;
        LDSM4(r0, r1, r2, r3, bHb + off);
        bHf[p*2][0] = r0; bHf[p*2][1] = r1; bHf[p*2+1][0] = r2; bHf[p*2+1][1] = r3;
        LDSM4(r0, r1, r2, r3, bLb + off);
        bLf[p*2][0] = r0; bLf[p*2][1] = r1; bLf[p*2+1][0] = r2; bLf[p*2+1][1] = r3;
    }
    #pragma unroll
    for (int mi = 0; mi < MT; mi++)
        #pragma unroll
        for (int nj = 0; nj < 4; nj++) {
            mma16816(acc[mi][nj], aH[mi][0], aH[mi][1], aH[mi][2], aH[mi][3], bHf[nj][0], bHf[nj][1]);
            mma16816(acc[mi][nj], aH[mi][0], aH[mi][1], aH[mi][2], aH[mi][3], bLf[nj][0], bLf[nj][1]);
            mma16816(acc[mi][nj], aL[mi][0], aL[mi][1], aL[mi][2], aL[mi][3], bHf[nj][0], bHf[nj][1]);
        }
}

// load nrows x 32 bf16 chunk into smem tile (stride 40 elems) via cp.async
__device__ __forceinline__ void ld_tile32(uint32_t sdst, const bf16* g, size_t rstride, int nrows) {
    int tid = threadIdx.x;
    int tot = nrows * 4;
    for (int u = tid; u < tot; u += 256) {
        int r = u >> 2, c = u & 3;
        uint32_t dst = sdst + (uint32_t)(r*80 + c*16);
        const bf16* src = g + (size_t)r * rstride + (c << 3);
        asm volatile("cp.async.cg.shared.global [%0], [%1], 16;" :: "r"(dst), "l"(src) : "memory");
    }
}
#define CPA_COMMIT() asm volatile("cp.async.commit_group;" ::: "memory")
#define CPA_WAIT1()  asm volatile("cp.async.wait_group 1;" ::: "memory")
#define CPA_WAIT0()  asm volatile("cp.async.wait_group 0;" ::: "memory")

__device__ __forceinline__ void split2(float v, bf16& h, bf16& l) {
    h = __float2bfloat16(v);
    l = __float2bfloat16(v - __bfloat162float(h));
}
__device__ __forceinline__ uint32_t pack2(bf16 a, bf16 b) {
    return (uint32_t)__bfloat16_as_ushort(a) | ((uint32_t)__bfloat16_as_ushort(b) << 16);
}

// ============================================================
// fp32 -> bf16 hi/lo split conversion. n4 = n/4
// ============================================================
__global__ void conv_kernel(const float* __restrict__ s, bf16* __restrict__ h,
                            bf16* __restrict__ l, int n4) {
    int i = blockIdx.x * 256 + threadIdx.x;
    if (i >= n4) return;
    float4 v = ((const float4*)s)[i];
    bf16 h0, h1, h2, h3, l0, l1, l2, l3;
    split2(v.x, h0, l0); split2(v.y, h1, l1); split2(v.z, h2, l2); split2(v.w, h3, l3);
    uint2 hp, lp;
    hp.x = pack2(h0, h1); hp.y = pack2(h2, h3);
    lp.x = pack2(l0, l1); lp.y = pack2(l2, l3);
    ((uint2*)h)[i] = hp;
    ((uint2*)l)[i] = lp;
}

// ============================================================
// proj: 128x128 tile of (xt @ W^T + b) via warp mma. grid(8,32,4) block 256
// smem: 2 x {AH,AL,BH,BL} of 128x40 bf16 = 81920 B
// ============================================================
__global__ void __launch_bounds__(256) proj_mm(
    const float* __restrict__ b0, const float* __restrict__ b1,
    const float* __restrict__ b2, const float* __restrict__ b3)
{
    extern __shared__ uint8_t dyn[];
    uint32_t sb = s2u(dyn);
    int tid = threadIdx.x, wid = tid >> 5, lane = tid & 31;

    int w = blockIdx.z;
    const bf16* WHp = (w==0)?WqH:(w==1)?WkH:(w==2)?WvH:WcH;
    const bf16* WLp = (w==0)?WqL:(w==1)?WkL:(w==2)?WvL:WcL;
    const float* bias = (w==0)?b0:(w==1)?b1:(w==2)?b2:b3;

    int m0 = blockIdx.y * 128, n0 = blockIdx.x * 128;
    int b_ = m0 >> 10, i0 = m0 & 1023;

    const bf16* aH = XH + (size_t)(b_*SS + i0 + 1)*EE;
    const bf16* aL = XL + (size_t)(b_*SS + i0 + 1)*EE;
    const bf16* bH = WHp + (size_t)n0*EE;
    const bf16* bL = WLp + (size_t)n0*EE;

    float acc[4][4][4] = {};
    int wm = wid & 1, wn = wid >> 1;
    int mrow0 = wm*64, ncol0 = wn*32;

    ld_tile32(sb,         aH, EE, 128);
    ld_tile32(sb + 10240, aL, EE, 128);
    ld_tile32(sb + 20480, bH, EE, 128);
    ld_tile32(sb + 30720, bL, EE, 128);
    CPA_COMMIT();
    int buf = 0;
    for (int ch = 0; ch < 32; ch++) {
        if (ch + 1 < 32) {
            uint32_t nb = sb + (buf^1)*40960;
            int kt = (ch + 1) * 32;
            ld_tile32(nb,         aH + kt, EE, 128);
            ld_tile32(nb + 10240, aL + kt, EE, 128);
            ld_tile32(nb + 20480, bH + kt, EE, 128);
            ld_tile32(nb + 30720, bL + kt, EE, 128);
            CPA_COMMIT();
            CPA_WAIT1();
        } else CPA_WAIT0();
        __syncthreads();
        uint32_t base = sb + buf*40960;
        wmma_step<4>(acc, base, base+10240, base+20480, base+30720, mrow0, ncol0, 0,  lane);
        wmma_step<4>(acc, base, base+10240, base+20480, base+30720, mrow0, ncol0, 16, lane);
        __syncthreads();
        buf ^= 1;
    }

    // epilogue: bias, split, scatter to head layouts
    int rbase = mrow0 + (lane >> 2);
    int cbase = ncol0 + (lane & 3)*2;
    #pragma unroll
    for (int mi = 0; mi < 4; mi++)
        #pragma unroll
        for (int half = 0; half < 2; half++) {
            int i = i0 + rbase + mi*16 + half*8;
            #pragma unroll
            for (int nj = 0; nj < 4; nj++) {
                int col = n0 + cbase + nj*8;
                int h2 = col >> 6, d2 = col & 63;
                float v0 = acc[mi][nj][half*2]   + bias[col];
                float v1 = acc[mi][nj][half*2+1] + bias[col+1];
                bf16 h0v, l0v, h1v, l1v;
                split2(v0, h0v, l0v); split2(v1, h1v, l1v);
                size_t qi = ((size_t)(b_*HH + h2)*SQ + i)*DH + d2;
                size_t ti = ((size_t)(b_*HH + h2)*DH + d2)*SQ + i;
                if (w == 0) {
                    *(float2*)&QS[qi] = make_float2(v0, v1);
                    *(uint32_t*)&QH[qi] = pack2(h0v, h1v);
                    *(uint32_t*)&QL[qi] = pack2(l0v, l1v);
                } else if (w == 1) {
                    *(float2*)&KS[qi] = make_float2(v0, v1);
                    *(uint32_t*)&KH[qi] = pack2(h0v, h1v);
                    *(uint32_t*)&KL[qi] = pack2(l0v, l1v);
                } else if (w == 2) {
                    *(float2*)&VS[qi] = make_float2(v0, v1);
                    VTH[ti] = h0v;      VTL[ti] = l0v;
                    VTH[ti + SQ] = h1v; VTL[ti + SQ] = l1v;
                } else {
                    CPTH[ti] = h0v;      CPTL[ti] = l0v;
                    CPTH[ti + SQ] = h1v; CPTL[ti + SQ] = l1v;
                }
            }
        }
}

// ============================================================
// logits: (Q K^T)*rsqrt(64*qn2). 128x128 tile, K=64. grid(8,8,64)
// ============================================================
__global__ void __launch_bounds__(256) logits_mm(float* __restrict__ attn)
{
    extern __shared__ uint8_t dyn[];
    uint32_t sb = s2u(dyn);
    int tid = threadIdx.x, wid = tid >> 5, lane = tid & 31;
    int bh = blockIdx.z;
    int m0 = blockIdx.y * 128, n0 = blockIdx.x * 128;

    size_t base = (size_t)bh*SQ*DH;
    const bf16* aH = QH + base + (size_t)m0*DH;
    const bf16* aL = QL + base + (size_t)m0*DH;
    const bf16* bH = KH + base + (size_t)n0*DH;
    const bf16* bL = KL + base + (size_t)n0*DH;

    float acc[4][4][4] = {};
    int wm = wid & 1, wn = wid >> 1;
    int mrow0 = wm*64, ncol0 = wn*32;

    ld_tile32(sb,         aH, DH, 128);
    ld_tile32(sb + 10240, aL, DH, 128);
    ld_tile32(sb + 20480, bH, DH, 128);
    ld_tile32(sb + 30720, bL, DH, 128);
    CPA_COMMIT();
    int buf = 0;
    for (int ch = 0; ch < 2; ch++) {
        if (ch == 0) {
            uint32_t nb = sb + 40960;
            ld_tile32(nb,         aH + 32, DH, 128);
            ld_tile32(nb + 10240, aL + 32, DH, 128);
            ld_tile32(nb + 20480, bH + 32, DH, 128);
            ld_tile32(nb + 30720, bL + 32, DH, 128);
            CPA_COMMIT();
            CPA_WAIT1();
        } else CPA_WAIT0();
        __syncthreads();
        uint32_t tb = sb + buf*40960;
        wmma_step<4>(acc, tb, tb+10240, tb+20480, tb+30720, mrow0, ncol0, 0,  lane);
        wmma_step<4>(acc, tb, tb+10240, tb+20480, tb+30720, mrow0, ncol0, 16, lane);
        __syncthreads();
        buf ^= 1;
    }

    int rbase = mrow0 + (lane >> 2);
    int cbase = ncol0 + (lane & 3)*2;
    #pragma unroll
    for (int mi = 0; mi < 4; mi++)
        #pragma unroll
        for (int half = 0; half < 2; half++) {
            int row = m0 + rbase + mi*16 + half*8;
            float sc = rsqrtf(64.0f * QN2[(size_t)bh*SQ + row]);
            float* orow = attn + ((size_t)bh*SQ + row)*SQ + n0;
            #pragma unroll
            for (int nj = 0; nj < 4; nj++) {
                *(float2*)&orow[cbase + nj*8] =
                    make_float2(acc[mi][nj][half*2]*sc, acc[mi][nj][half*2+1]*sc);
            }
        }
}

// ============================================================
// values: [attn|ac2o] @ [V^T;CP^T] as K=2048 GEMM. M=128,N=64. grid(8,64)
// smem/buffer: AH,AL 128x40 + BH,BL 64x40 = 30720; x2 = 61440
// ============================================================
__global__ void __launch_bounds__(256) values_mm()
{
    extern __shared__ uint8_t dyn[];
    uint32_t sb = s2u(dyn);
    int tid = threadIdx.x, wid = tid >> 5, lane = tid & 31;
    int bh = blockIdx.y;
    int m0 = blockIdx.x * 128;

    size_t abase = (size_t)bh*SQ*SQ + (size_t)m0*SQ;
    size_t tbase = (size_t)bh*DH*SQ;

    float acc[2][4][4] = {};
    int wm = wid & 3, wn = wid >> 2;
    int mrow0 = wm*32, ncol0 = wn*32;

    #define VLOAD(bufb, CH) do { \
        int kt_ = (CH) * 32; \
        const bf16 *ah_, *al_, *bh_, *bl_; \
        if (kt_ < 1024) { \
            ah_ = ATH + abase + kt_; al_ = ATL + abase + kt_; \
            bh_ = VTH + tbase + kt_; bl_ = VTL + tbase + kt_; \
        } else { \
            ah_ = ACH + abase + (kt_ - 1024); al_ = ACL + abase + (kt_ - 1024); \
            bh_ = CPTH + tbase + (kt_ - 1024); bl_ = CPTL + tbase + (kt_ - 1024); \
        } \
        ld_tile32((bufb),         ah_, SQ, 128); \
        ld_tile32((bufb) + 10240, al_, SQ, 128); \
        ld_tile32((bufb) + 20480, bh_, SQ, 64); \
        ld_tile32((bufb) + 25600, bl_, SQ, 64); \
        CPA_COMMIT(); \
    } while (0)

    VLOAD(sb, 0);
    int buf = 0;
    for (int ch = 0; ch < 64; ch++) {
        if (ch + 1 < 64) { VLOAD(sb + (buf^1)*30720, ch + 1); CPA_WAIT1(); }
        else CPA_WAIT0();
        __syncthreads();
        uint32_t tb = sb + buf*30720;
        wmma_step<2>(acc, tb, tb+10240, tb+20480, tb+25600, mrow0, ncol0, 0,  lane);
        wmma_step<2>(acc, tb, tb+10240, tb+20480, tb+25600, mrow0, ncol0, 16, lane);
        __syncthreads();
        buf ^= 1;
    }
    #undef VLOAD

    int b_ = bh / HH, h_ = bh % HH;
    int rbase = mrow0 + (lane >> 2);
    int cbase = ncol0 + (lane & 3)*2;
    #pragma unroll
    for (int mi = 0; mi < 2; mi++)
        #pragma unroll
        for (int half = 0; half < 2; half++) {
            int i = m0 + rbase + mi*16 + half*8;
            size_t ob = (size_t)(b_*SS + 1 + i)*EE + h_*DH;
            #pragma unroll
            for (int nj = 0; nj < 4; nj++) {
                int col = cbase + nj*8;
                float v0 = acc[mi][nj][half*2], v1 = acc[mi][nj][half*2+1];
                bf16 h0v, l0v, h1v, l1v;
                split2(v0, h0v, l0v); split2(v1, h1v, l1v);
                *(uint32_t*)&VALSH[ob + col] = pack2(h0v, h1v);
                *(uint32_t*)&VALSL[ob + col] = pack2(l0v, l1v);
            }
        }
}

// ============================================================
// out: VALS @ Wo^T + bo. grid(8,33), M guard at 4100
// ============================================================
__global__ void __launch_bounds__(256) out_mm(const float* __restrict__ bo,
                                             float* __restrict__ out)
{
    extern __shared__ uint8_t dyn[];
    uint32_t sb = s2u(dyn);
    int tid = threadIdx.x, wid = tid >> 5, lane = tid & 31;
    int m0 = blockIdx.y * 128, n0 = blockIdx.x * 128;

    const bf16* aH = VALSH + (size_t)m0*EE;
    const bf16* aL = VALSL + (size_t)m0*EE;
    const bf16* bH = WoH + (size_t)n0*EE;
    const bf16* bL = WoL + (size_t)n0*EE;

    float acc[4][4][4] = {};
    int wm = wid & 1, wn = wid >> 1;
    int mrow0 = wm*64, ncol0 = wn*32;

    ld_tile32(sb,         aH, EE, 128);
    ld_tile32(sb + 10240, aL, EE, 128);
    ld_tile32(sb + 20480, bH, EE, 128);
    ld_tile32(sb + 30720, bL, EE, 128);
    CPA_COMMIT();
    int buf = 0;
    for (int ch = 0; ch < 32; ch++) {
        if (ch + 1 < 32) {
            uint32_t nb = sb + (buf^1)*40960;
            int kt = (ch + 1) * 32;
            ld_tile32(nb,         aH + kt, EE, 128);
            ld_tile32(nb + 10240, aL + kt, EE, 128);
            ld_tile32(nb + 20480, bH + kt, EE, 128);
            ld_tile32(nb + 30720, bL + kt, EE, 128);
            CPA_COMMIT();
            CPA_WAIT1();
        } else CPA_WAIT0();
        __syncthreads();
        uint32_t base = sb + buf*40960;
        wmma_step<4>(acc, base, base+10240, base+20480, base+30720, mrow0, ncol0, 0,  lane);
        wmma_step<4>(acc, base, base+10240, base+20480, base+30720, mrow0, ncol0, 16, lane);
        __syncthreads();
        buf ^= 1;
    }

    int rbase = mrow0 + (lane >> 2);
    int cbase = ncol0 + (lane & 3)*2;
    #pragma unroll
    for (int mi = 0; mi < 4; mi++)
        #pragma unroll
        for (int half = 0; half < 2; half++) {
            int mr = m0 + rbase + mi*16 + half*8;
            if (mr >= MROWS_OUT) continue;
            #pragma unroll
            for (int nj = 0; nj < 4; nj++) {
                int col = n0 + cbase + nj*8;
                *(float2*)&out[(size_t)mr*EE + col] =
                    make_float2(acc[mi][nj][half*2] + bo[col],
                                acc[mi][nj][half*2+1] + bo[col+1]);
            }
        }
}

// ============================================================
// cls token projection + CN2. grid BH, block 64
// ============================================================
__global__ void clsproj_kernel(const float* __restrict__ x,
                               const float* __restrict__ Wq,
                               const float* __restrict__ bq) {
    int bh = blockIdx.x;
    int b_ = bh / HH, h_ = bh % HH;
    int d  = threadIdx.x;
    int j  = h_*DH + d;
    const float* xr = x  + (size_t)(b_*SS)*EE;
    const float* wr = Wq + (size_t)j*EE;
    float s = 0.f;
    for (int e = 0; e < EE; e += 4) {
        float4 xv = *(const float4*)(xr + e);
        float4 wv = *(const float4*)(wr + e);
        s += xv.x*wv.x + xv.y*wv.y + xv.z*wv.z + xv.w*wv.w;
    }
    s += bq[j];
    CVEC[bh*DH + d] = s;
    __shared__ float red[64];
    red[d] = s*s; __syncthreads();
    for (int o = 32; o > 0; o >>= 1) { if (d < o) red[d] += red[d+o]; __syncthreads(); }
    if (d == 0) CN2[bh] = fmaxf(red[0], EPSF);
}

// ============================================================
// per-row q stats: QN2 and CQ. grid BH*SQ/8, block 256
// ============================================================
__global__ void qstats_kernel() {
    int row  = blockIdx.x*8 + (threadIdx.x >> 5);
    int lane = threadIdx.x & 31;
    int bh   = row >> 10;
    const float* qr = QS   + (size_t)row*DH;
    const float* cv = CVEC + bh*DH;
    float n2 = 0.f, cq = 0.f;
    #pragma unroll
    for (int d = lane; d < DH; d += 32) {
        float qv = qr[d];
        n2 += qv*qv;
        cq += qv*cv[d];
    }
    #pragma unroll
    for (int o = 16; o > 0; o >>= 1) {
        n2 += __shfl_xor_sync(0xffffffffu, n2, o);
        cq += __shfl_xor_sync(0xffffffffu, cq, o);
    }
    if (lane == 0) { QN2[row] = fmaxf(n2, EPSF); CQg[row] = cq; }
}

// ============================================================
// dual softmax: attn (in place fp32) + hi/lo splits of attn & attn_c2o
// grid BH*SQ, block 256
// ============================================================
__global__ void softmax_kernel(float* __restrict__ attn) {
    int row = blockIdx.x;
    int bh  = row >> 10;
    float* lrow = attn + (size_t)row*SQ;
    size_t sbase = (size_t)row*SQ;
    int tid = threadIdx.x;
    __shared__ float red[256];

    float l[4], cq[4];
    #pragma unroll
    for (int p = 0; p < 4; p++) {
        int j = tid + p*256;
        l[p]  = lrow[j];
        cq[p] = CQg[(size_t)bh*SQ + j];
    }

    float m = fmaxf(fmaxf(l[0],l[1]), fmaxf(l[2],l[3]));
    red[tid] = m; __syncthreads();
    #pragma unroll
    for (int o = 128; o > 0; o >>= 1) { if (tid < o) red[tid] = fmaxf(red[tid], red[tid+o]); __syncthreads(); }
    m = red[0]; __syncthreads();
    float e1[4], s1 = 0.f;
    #pragma unroll
    for (int p = 0; p < 4; p++) { e1[p] = __expf(l[p] - m); s1 += e1[p]; }
    red[tid] = s1; __syncthreads();
    #pragma unroll
    for (int o = 128; o > 0; o >>= 1) { if (tid < o) red[tid] += red[tid+o]; __syncthreads(); }
    float inv1 = 1.0f / red[0]; __syncthreads();

    float r = rsqrtf(QN2[row] * CN2[bh]);
    float l2[4];
    #pragma unroll
    for (int p = 0; p < 4; p++) l2[p] = l[p]*cq[p]*r;
    float m2 = fmaxf(fmaxf(l2[0],l2[1]), fmaxf(l2[2],l2[3]));
    red[tid] = m2; __syncthreads();
    #pragma unroll
    for (int o = 128; o > 0; o >>= 1) { if (tid < o) red[tid] = fmaxf(red[tid], red[tid+o]); __syncthreads(); }
    m2 = red[0]; __syncthreads();
    float e2[4], s2 = 0.f;
    #pragma unroll
    for (int p = 0; p < 4; p++) { e2[p] = __expf(l2[p] - m2); s2 += e2[p]; }
    red[tid] = s2; __syncthreads();
    #pragma unroll
    for (int o = 128; o > 0; o >>= 1) { if (tid < o) red[tid] += red[tid+o]; __syncthreads(); }
    float inv2 = 1.0f / red[0];

    #pragma unroll
    for (int p = 0; p < 4; p++) {
        int j = tid + p*256;
        float a1 = e1[p]*inv1;
        float a2 = e2[p]*inv2;
        lrow[j] = a1;
        bf16 h1, o1, h2, o2;
        split2(a1, h1, o1);
        split2(a2, h2, o2);
        ATH[sbase + j] = h1; ATL[sbase + j] = o1;
        ACH[sbase + j] = h2; ACL[sbase + j] = o2;
    }
}

// ============================================================
// cls path: ck softmax -> cls_out row (hi/lo into VALS). grid BH, block 256
// ============================================================
__global__ void cls_kernel() {
    int bh = blockIdx.x;
    int tid = threadIdx.x;
    const float* Kp = KS + (size_t)bh*SQ*DH;
    const float* Vp = VS + (size_t)bh*SQ*DH;
    __shared__ float p_s[SQ];
    __shared__ float red[256];
    __shared__ float c_s[DH];
    if (tid < DH) c_s[tid] = CVEC[bh*DH + tid];
    __syncthreads();

    float scale = rsqrtf(64.0f * CN2[bh]);
    float lo[4];
    #pragma unroll
    for (int p = 0; p < 4; p++) {
        int j = tid + p*256;
        const float* kr = Kp + (size_t)j*DH;
        float s = 0.f;
        #pragma unroll
        for (int d = 0; d < DH; d += 4) {
            float4 kv = *(const float4*)(kr + d);
            s += c_s[d]*kv.x + c_s[d+1]*kv.y + c_s[d+2]*kv.z + c_s[d+3]*kv.w;
        }
        lo[p] = s * scale;
    }
    float m = fmaxf(fmaxf(lo[0],lo[1]), fmaxf(lo[2],lo[3]));
    red[tid] = m; __syncthreads();
    #pragma unroll
    for (int o = 128; o > 0; o >>= 1) { if (tid < o) red[tid] = fmaxf(red[tid], red[tid+o]); __syncthreads(); }
    m = red[0]; __syncthreads();
    float e[4], s = 0.f;
    #pragma unroll
    for (int p = 0; p < 4; p++) { e[p] = __expf(lo[p] - m); s += e[p]; }
    red[tid] = s; __syncthreads();
    #pragma unroll
    for (int o = 128; o > 0; o >>= 1) { if (tid < o) red[tid] += red[tid+o]; __syncthreads(); }
    float inv = 1.0f / red[0]; __syncthreads();
    #pragma unroll
    for (int p = 0; p < 4; p++) p_s[tid + p*256] = e[p]*inv;
    __syncthreads();

    int d = tid & 63, g = tid >> 6;
    float acc = 0.f;
    for (int j = g*256; j < (g+1)*256; j++) acc += p_s[j] * Vp[(size_t)j*DH + d];
    red[tid] = acc; __syncthreads();
    if (g == 0) {
        float rsum = red[tid] + red[tid+64] + red[tid+128] + red[tid+192];
        int b_ = bh / HH, h_ = bh % HH;
        bf16 hi, lov; split2(rsum, hi, lov);
        size_t idx = (size_t)(b_*SS)*EE + h_*DH + d;
        VALSH[idx] = hi;
        VALSL[idx] = lov;
    }
}

extern "C" void kernel_launch(void* const* d_in, const int* in_sizes, int n_in,
                              void* d_out, int out_size) {
    const float* x  = (const float*)d_in[0];
    const float* Wq = (const float*)d_in[1];
    const float* bq = (const float*)d_in[2];
    const float* Wk = (const float*)d_in[3];
    const float* bk = (const float*)d_in[4];
    const float* Wv = (const float*)d_in[5];
    const float* bv = (const float*)d_in[6];
    const float* Wo = (const float*)d_in[7];
    const float* bo = (const float*)d_in[8];
    const float* Wc = (const float*)d_in[9];
    const float* bc = (const float*)d_in[10];

    float* out  = (float*)d_out;
    float* attn = out + (size_t)BB*SS*EE;

    cudaFuncSetAttribute(proj_mm,   cudaFuncAttributeMaxDynamicSharedMemorySize, 81920);
    cudaFuncSetAttribute(logits_mm, cudaFuncAttributeMaxDynamicSharedMemorySize, 81920);
    cudaFuncSetAttribute(out_mm,    cudaFuncAttributeMaxDynamicSharedMemorySize, 81920);
    cudaFuncSetAttribute(values_mm, cudaFuncAttributeMaxDynamicSharedMemorySize, 61440);

    bf16 *xh, *xl, *wqh, *wql, *wkh, *wkl, *wvh, *wvl, *wch, *wcl, *woh, *wol;
    cudaGetSymbolAddress((void**)&xh, XH);   cudaGetSymbolAddress((void**)&xl, XL);
    cudaGetSymbolAddress((void**)&wqh, WqH); cudaGetSymbolAddress((void**)&wql, WqL);
    cudaGetSymbolAddress((void**)&wkh, WkH); cudaGetSymbolAddress((void**)&wkl, WkL);
    cudaGetSymbolAddress((void**)&wvh, WvH); cudaGetSymbolAddress((void**)&wvl, WvL);
    cudaGetSymbolAddress((void**)&wch, WcH); cudaGetSymbolAddress((void**)&wcl, WcL);
    cudaGetSymbolAddress((void**)&woh, WoH); cudaGetSymbolAddress((void**)&wol, WoL);

    int nx4 = BB*SS*EE/4, nw4 = EE*EE/4;
    conv_kernel<<<(nx4+255)/256, 256>>>(x,  xh,  xl,  nx4);
    conv_kernel<<<(nw4+255)/256, 256>>>(Wq, wqh, wql, nw4);
    conv_kernel<<<(nw4+255)/256, 256>>>(Wk, wkh, wkl, nw4);
    conv_kernel<<<(nw4+255)/256, 256>>>(Wv, wvh, wvl, nw4);
    conv_kernel<<<(nw4+255)/256, 256>>>(Wc, wch, wcl, nw4);
    conv_kernel<<<(nw4+255)/256, 256>>>(Wo, woh, wol, nw4);

    proj_mm<<<dim3(8,32,4), 256, 81920>>>(bq, bk, bv, bc);
    clsproj_kernel<<<BH, 64>>>(x, Wq, bq);
    qstats_kernel<<<BH*SQ/8, 256>>>();
    logits_mm<<<dim3(8,8,BH), 256, 81920>>>(attn);
    softmax_kernel<<<BH*SQ, 256>>>(attn);
    values_mm<<<dim3(8,BH), 256, 61440>>>();
    cls_kernel<<<BH, 256>>>();
    out_mm<<<dim3(8,33), 256, 81920>>>(bo, out);
}